// round 8
// baseline (speedup 1.0000x reference)
#include <cuda_runtime.h>

#define BATCH 8
#define NCH   6
#define HH    1024
#define WW    1024
#define TX    64
#define TY    64
#define HY    68      // halo rows: [by-2, by+66)
#define NPIX  (8.0f * 1024.0f * 1024.0f)
#define PIX_PER_B (HH * WW)          // 1<<20
#define CH_STRIDE4 (PIX_PER_B / 4)   // 262144
#define NSTENCIL 2048                // total stencil tiles

__device__ unsigned g_code4[(BATCH * PIX_PER_B) / 4];   // 8 MiB
__device__ int   g_cnt[BATCH];    // classify blocks completed per batch
__device__ int   g_done;          // stencil tiles completed
__device__ float g_partial;       // loss accumulator

// One fused kernel: 4096 blocks x 512 threads.
// Block bid: classifies rows [2*bid, 2*bid+1] (batch = bid>>9, 512 blocks/batch).
// Blocks with (bid & 511) >= 256 additionally process one 64x64 stencil tile of
// their own batch after that batch's classify completes (producer-consumer via
// g_cnt; release = per-thread threadfence + counter, acquire = ld.acquire.gpu).
// Deadlock-free under FIFO block issue: every block runs classify before any
// wait; at most 256 spinners per batch < 296 resident slots (>=2 blocks/SM).
__global__ __launch_bounds__(512, 2) void dcl_fused(
    const float* __restrict__ pred, const void* __restrict__ tgt,
    float* __restrict__ out)
{
    const int tid   = threadIdx.x;
    const int bid   = blockIdx.x;
    const int batch = bid >> 9;

    // ================= Phase 1: classify (streaming argmax + pack) ==========
    {
        // Targets in [0,5]; little-endian int64 => odd 32-bit words of the
        // first 64 elements all zero. P(false positive int32) = (1/6)^32 ~ 0.
        const int lane  = tid & 31;
        const int probe = ((const int*)tgt)[2 * lane + 1];
        const int is64  = (__ballot_sync(0xffffffffu, probe != 0) == 0u);

        const unsigned t   = (unsigned)bid * 512u + tid;   // pixel4 index
        const unsigned off = t & 0x3FFFFu;

        const float4* pp = (const float4*)pred + (size_t)batch * NCH * CH_STRIDE4 + off;
        float4 v[NCH];
        #pragma unroll
        for (int ch = 0; ch < NCH; ++ch) v[ch] = pp[(size_t)ch * CH_STRIDE4];

        int t0, t1, t2, t3;
        if (is64) {
            const int4* tp = (const int4*)tgt + (size_t)t * 2;
            const int4 q0 = tp[0], q1 = tp[1];
            t0 = q0.x; t1 = q0.z; t2 = q1.x; t3 = q1.z;
        } else {
            const int4 q = ((const int4*)tgt)[t];
            t0 = q.x; t1 = q.y; t2 = q.z; t3 = q.w;
        }

        int i0 = 0, i1 = 0, i2 = 0, i3 = 0;
        float m0 = v[0].x, m1 = v[0].y, m2 = v[0].z, m3 = v[0].w;
        #pragma unroll
        for (int ch = 1; ch < NCH; ++ch) {
            if (v[ch].x > m0) { m0 = v[ch].x; i0 = ch; }
            if (v[ch].y > m1) { m1 = v[ch].y; i1 = ch; }
            if (v[ch].z > m2) { m2 = v[ch].z; i2 = ch; }
            if (v[ch].w > m3) { m3 = v[ch].w; i3 = ch; }
        }

        g_code4[t] = (unsigned)(i0 | (t0 << 4))
                   | ((unsigned)(i1 | (t1 << 4)) << 8)
                   | ((unsigned)(i2 | (t2 << 4)) << 16)
                   | ((unsigned)(i3 | (t3 << 4)) << 24);
    }

    // Release: make this block's code words globally visible, then count it.
    __threadfence();
    __syncthreads();
    if (tid == 0) atomicAdd(&g_cnt[batch], 1);

    const int r = bid & 511;
    if (r < 256) return;          // first half of each batch: classify only

    // ================= Wait: own batch fully classified ======================
    if (tid == 0) {
        int v;
        do {
            asm volatile("ld.acquire.gpu.s32 %0, [%1];"
                         : "=r"(v) : "l"(g_cnt + batch) : "memory");
            if (v >= 512) break;
            __nanosleep(128);
        } while (1);
    }
    __syncthreads();

    // ================= Phase 2: stencil tile + reduce ========================
    // hbuf[r][c] = uint2{a,b}, 16-bit fields:
    //   a = h5sum(cv) | h5sum(tv)<<16 (<=25); b = h5sum(cv2) | h5sum(tv2)<<16 (<=125)
    // Vertical 5-sums: a-fields <= 125, b-fields <= 625 — no carry.
    __shared__ uint2 hbuf[HY][TX];

    const int tile = r - 256;               // 0..255
    const int bx   = (tile & 15) * TX;
    const int by   = (tile >> 4) * TY;
    const unsigned base_w = (unsigned)batch << 18;

    for (int i = tid; i < HY * (TX / 4); i += 512) {
        const int rr = i >> 4;              // halo row 0..67
        const int cw = i & 15;              // word-col within tile
        const int gy = by + rr - 2;
        unsigned wm = 0, w0 = 0, wp = 0;
        if ((unsigned)gy < (unsigned)HH) {
            const unsigned rowbase = base_w + ((unsigned)gy << 8);
            const int wc = (bx >> 2) + cw;  // 0..255
            if (wc > 0)   wm = g_code4[rowbase + wc - 1];
            w0 = g_code4[rowbase + wc];
            if (wc < 255) wp = g_code4[rowbase + wc + 1];
        }
        unsigned e[8];
        e[0] = (wm >> 16) & 255u;  e[1] = wm >> 24;
        e[2] =  w0        & 255u;  e[3] = (w0 >> 8) & 255u;
        e[4] = (w0 >> 16) & 255u;  e[5] =  w0 >> 24;
        e[6] =  wp        & 255u;  e[7] = (wp >> 8) & 255u;
        unsigned ma[8], mb[8];
        #pragma unroll
        for (int j = 0; j < 8; ++j) {
            const unsigned cv = e[j] & 15u, tv = e[j] >> 4;
            ma[j] = cv + (tv << 16);
            mb[j] = cv * cv + ((tv * tv) << 16);
        }
        unsigned sa = ma[0] + ma[1] + ma[2] + ma[3] + ma[4];
        unsigned sb = mb[0] + mb[1] + mb[2] + mb[3] + mb[4];
        uint4 lo, hi;
        lo.x = sa; lo.y = sb; sa += ma[5] - ma[0]; sb += mb[5] - mb[0];
        lo.z = sa; lo.w = sb; sa += ma[6] - ma[1]; sb += mb[6] - mb[1];
        hi.x = sa; hi.y = sb; sa += ma[7] - ma[2]; sb += mb[7] - mb[2];
        hi.z = sa; hi.w = sb;
        uint4* dst = (uint4*)&hbuf[rr][cw * 4];
        dst[0] = lo; dst[1] = hi;
    }
    __syncthreads();

    // Vertical sliding 5-window: 1 col x 8 rows per thread.
    const int c  = tid & 63;
    const int r0 = (tid >> 6) * 8;

    unsigned a[12], b[12];
    #pragma unroll
    for (int d = 0; d < 12; ++d) {
        const uint2 w = hbuf[r0 + d][c];
        a[d] = w.x; b[d] = w.y;
    }
    unsigned sa = a[0] + a[1] + a[2] + a[3] + a[4];
    unsigned sb = b[0] + b[1] + b[2] + b[3] + b[4];

    int   acc_i = 0;
    float acc_s = 0.0f;
    #pragma unroll
    for (int rr = 0; rr < 8; ++rr) {
        const int s1c = (int)(sa & 0xFFFFu), s1t = (int)(sa >> 16);
        const int s2c = (int)(sb & 0xFFFFu), s2t = (int)(sb >> 16);
        const int np = 25 * s2c - s1c * s1c;   // exact, in [0, 15625]
        const int nt = 25 * s2t - s1t * s1t;
        acc_i += np + nt;
        // (sqrt(np/600)-sqrt(nt/600))^2 = (np + nt - 2*sqrt(np*nt))/600
        const float p = (float)(np * nt);
        float s;
        asm("sqrt.approx.f32 %0, %1;" : "=f"(s) : "f"(p));
        acc_s += s;
        if (rr < 7) { sa += a[rr + 5] - a[rr]; sb += b[rr + 5] - b[rr]; }
    }

    float acc = fmaf(-2.0f, acc_s, (float)acc_i) * (1.0f / (600.0f * NPIX));

    #pragma unroll
    for (int o = 16; o > 0; o >>= 1)
        acc += __shfl_down_sync(0xffffffffu, acc, o);

    __shared__ float warpsum[16];
    if ((tid & 31) == 0) warpsum[tid >> 5] = acc;
    __syncthreads();
    if (tid < 16) {
        float v = warpsum[tid];
        #pragma unroll
        for (int o = 8; o > 0; o >>= 1)
            v += __shfl_down_sync(0xffffu, v, o);
        if (tid == 0) {
            atomicAdd(&g_partial, v);
            __threadfence();
            const int old = atomicAdd(&g_done, 1);
            if (old == NSTENCIL - 1) {
                // All tiles done (each fenced before g_done inc): publish and
                // reset ALL state for the next graph replay.
                *out = *(volatile float*)&g_partial;
                g_partial = 0.0f;
                #pragma unroll
                for (int i = 0; i < BATCH; ++i) g_cnt[i] = 0;
                g_done = 0;
                __threadfence();
            }
        }
    }
}

extern "C" void kernel_launch(void* const* d_in, const int* in_sizes, int n_in,
                              void* d_out, int out_size) {
    const float* pred = (const float*)d_in[0];
    const void*  tgt  = d_in[1];
    float* out = (float*)d_out;

    dcl_fused<<<4096, 512>>>(pred, tgt, out);
}

// round 10
// speedup vs baseline: 1.0644x; 1.0644x over previous
#include <cuda_runtime.h>

#define BATCH 8
#define NCH   6
#define HH    1024
#define WW    1024
#define TX    64
#define TY    64
#define HY    68      // halo rows: [by-2, by+66)
#define NPIX  (8.0f * 1024.0f * 1024.0f)
#define PIX_PER_B (HH * WW)          // 1<<20
#define CH_STRIDE4 (PIX_PER_B / 4)   // 262144
#define NSTENCIL 2048

__device__ unsigned g_code4[(BATCH * PIX_PER_B) / 4];   // 8 MiB
__device__ int   g_cnt[BATCH];    // classify blocks completed per batch
__device__ int   g_done;          // stencil tiles completed
__device__ float g_partial;       // loss accumulator

// One fused kernel, 4096 blocks x 512 threads.
// Every block classifies its 2 rows of its batch (batch = bid>>9).
// Stencil tile assignment (shifted one batch back so waits are ~free):
//   bid in [512(b+1), 512(b+1)+256) -> tile (bid&255) of batch b, b=0..6
//   bid in [3840+256, 4096)         -> tile (bid&511)-256 of batch 7 (tail)
// A waiter on batch b-1 becomes resident only after all batch b-1 blocks have
// been issued (bid-ordered CTA issue), and classify has no dependencies, so
// the wait is short and deadlock is impossible.
__global__ __launch_bounds__(512, 2) void dcl_fused(
    const float* __restrict__ pred, const void* __restrict__ tgt,
    float* __restrict__ out)
{
    const int tid   = threadIdx.x;
    const int bid   = blockIdx.x;
    const int batch = bid >> 9;

    // ================= Phase 1: classify (streaming argmax + pack) ==========
    {
        // Targets in [0,5]; little-endian int64 => odd 32-bit words of the
        // first 64 elements all zero. P(false positive int32) = (1/6)^32 ~ 0.
        const int lane  = tid & 31;
        const int probe = ((const int*)tgt)[2 * lane + 1];
        const int is64  = (__ballot_sync(0xffffffffu, probe != 0) == 0u);

        const unsigned t   = (unsigned)bid * 512u + tid;   // pixel4 index
        const unsigned off = t & 0x3FFFFu;

        const float4* pp = (const float4*)pred + (size_t)batch * NCH * CH_STRIDE4 + off;
        float4 v[NCH];
        #pragma unroll
        for (int ch = 0; ch < NCH; ++ch) v[ch] = pp[(size_t)ch * CH_STRIDE4];

        int t0, t1, t2, t3;
        if (is64) {
            const int4* tp = (const int4*)tgt + (size_t)t * 2;
            const int4 q0 = tp[0], q1 = tp[1];
            t0 = q0.x; t1 = q0.z; t2 = q1.x; t3 = q1.z;
        } else {
            const int4 q = ((const int4*)tgt)[t];
            t0 = q.x; t1 = q.y; t2 = q.z; t3 = q.w;
        }

        int i0 = 0, i1 = 0, i2 = 0, i3 = 0;
        float m0 = v[0].x, m1 = v[0].y, m2 = v[0].z, m3 = v[0].w;
        #pragma unroll
        for (int ch = 1; ch < NCH; ++ch) {
            if (v[ch].x > m0) { m0 = v[ch].x; i0 = ch; }
            if (v[ch].y > m1) { m1 = v[ch].y; i1 = ch; }
            if (v[ch].z > m2) { m2 = v[ch].z; i2 = ch; }
            if (v[ch].w > m3) { m3 = v[ch].w; i3 = ch; }
        }

        g_code4[t] = (unsigned)(i0 | (t0 << 4))
                   | ((unsigned)(i1 | (t1 << 4)) << 8)
                   | ((unsigned)(i2 | (t2 << 4)) << 16)
                   | ((unsigned)(i3 | (t3 << 4)) << 24);
    }

    // Release: publish this block's code words, then count the block.
    __threadfence();
    __syncthreads();
    if (tid == 0) atomicAdd(&g_cnt[batch], 1);

    // ================= Stencil tile assignment ==============================
    const int half = bid & 511;
    int tb, tile;
    if (batch >= 1 && half < 256)       { tb = batch - 1; tile = half; }
    else if (batch == 7 && half >= 256) { tb = 7;         tile = half - 256; }
    else return;                        // classify-only block

    // Wait: target batch fully classified (usually already done for tb<7).
    if (tid == 0) {
        int v;
        do {
            asm volatile("ld.acquire.gpu.s32 %0, [%1];"
                         : "=r"(v) : "l"(g_cnt + tb) : "memory");
            if (v >= 512) break;
            __nanosleep(64);
        } while (1);
    }
    __syncthreads();

    // ================= Phase 2: stencil tile + reduce =======================
    // hbuf[r][c] = uint2{a,b}, 16-bit fields:
    //   a = h5sum(cv) | h5sum(tv)<<16 (<=25); b = h5sum(cv2)|h5sum(tv2)<<16 (<=125)
    // Vertical 5-sums: a-fields <= 125, b-fields <= 625 — no carry.
    __shared__ uint2 hbuf[HY][TX];

    const int bx = (tile & 15) * TX;
    const int by = (tile >> 4) * TY;
    const unsigned base_w = (unsigned)tb << 18;

    for (int i = tid; i < HY * (TX / 4); i += 512) {
        const int rr = i >> 4;              // halo row 0..67
        const int cw = i & 15;              // word-col within tile
        const int gy = by + rr - 2;
        unsigned wm = 0, w0 = 0, wp = 0;
        if ((unsigned)gy < (unsigned)HH) {
            const unsigned rowbase = base_w + ((unsigned)gy << 8);
            const int wc = (bx >> 2) + cw;  // 0..255
            if (wc > 0)   wm = g_code4[rowbase + wc - 1];
            w0 = g_code4[rowbase + wc];
            if (wc < 255) wp = g_code4[rowbase + wc + 1];
        }
        unsigned e[8];
        e[0] = (wm >> 16) & 255u;  e[1] = wm >> 24;
        e[2] =  w0        & 255u;  e[3] = (w0 >> 8) & 255u;
        e[4] = (w0 >> 16) & 255u;  e[5] =  w0 >> 24;
        e[6] =  wp        & 255u;  e[7] = (wp >> 8) & 255u;
        unsigned ma[8], mb[8];
        #pragma unroll
        for (int j = 0; j < 8; ++j) {
            const unsigned cv = e[j] & 15u, tv = e[j] >> 4;
            ma[j] = cv + (tv << 16);
            mb[j] = cv * cv + ((tv * tv) << 16);
        }
        unsigned sa = ma[0] + ma[1] + ma[2] + ma[3] + ma[4];
        unsigned sb = mb[0] + mb[1] + mb[2] + mb[3] + mb[4];
        uint4 lo, hi;
        lo.x = sa; lo.y = sb; sa += ma[5] - ma[0]; sb += mb[5] - mb[0];
        lo.z = sa; lo.w = sb; sa += ma[6] - ma[1]; sb += mb[6] - mb[1];
        hi.x = sa; hi.y = sb; sa += ma[7] - ma[2]; sb += mb[7] - mb[2];
        hi.z = sa; hi.w = sb;
        uint4* dst = (uint4*)&hbuf[rr][cw * 4];
        dst[0] = lo; dst[1] = hi;
    }
    __syncthreads();

    // Vertical sliding 5-window: 1 col x 8 rows per thread.
    const int c  = tid & 63;
    const int r0 = (tid >> 6) * 8;

    unsigned a[12], b[12];
    #pragma unroll
    for (int d = 0; d < 12; ++d) {
        const uint2 w = hbuf[r0 + d][c];
        a[d] = w.x; b[d] = w.y;
    }
    unsigned sa = a[0] + a[1] + a[2] + a[3] + a[4];
    unsigned sb = b[0] + b[1] + b[2] + b[3] + b[4];

    int   acc_i = 0;
    float acc_s = 0.0f;
    #pragma unroll
    for (int rr = 0; rr < 8; ++rr) {
        const int s1c = (int)(sa & 0xFFFFu), s1t = (int)(sa >> 16);
        const int s2c = (int)(sb & 0xFFFFu), s2t = (int)(sb >> 16);
        const int np = 25 * s2c - s1c * s1c;   // exact, in [0, 15625]
        const int nt = 25 * s2t - s1t * s1t;
        acc_i += np + nt;
        // (sqrt(np/600)-sqrt(nt/600))^2 = (np + nt - 2*sqrt(np*nt))/600
        const float p = (float)(np * nt);
        float s;
        asm("sqrt.approx.f32 %0, %1;" : "=f"(s) : "f"(p));
        acc_s += s;
        if (rr < 7) { sa += a[rr + 5] - a[rr]; sb += b[rr + 5] - b[rr]; }
    }

    float acc = fmaf(-2.0f, acc_s, (float)acc_i) * (1.0f / (600.0f * NPIX));

    #pragma unroll
    for (int o = 16; o > 0; o >>= 1)
        acc += __shfl_down_sync(0xffffffffu, acc, o);

    __shared__ float warpsum[16];
    if ((tid & 31) == 0) warpsum[tid >> 5] = acc;
    __syncthreads();
    if (tid < 16) {
        float v = warpsum[tid];
        #pragma unroll
        for (int o = 8; o > 0; o >>= 1)
            v += __shfl_down_sync(0xffffu, v, o);
        if (tid == 0) {
            atomicAdd(&g_partial, v);
            __threadfence();
            const int old = atomicAdd(&g_done, 1);
            if (old == NSTENCIL - 1) {
                // All tiles done (each fenced before its g_done inc): publish
                // and reset ALL state for the next graph replay.
                *out = *(volatile float*)&g_partial;
                g_partial = 0.0f;
                #pragma unroll
                for (int i = 0; i < BATCH; ++i) g_cnt[i] = 0;
                g_done = 0;
                __threadfence();
            }
        }
    }
}

extern "C" void kernel_launch(void* const* d_in, const int* in_sizes, int n_in,
                              void* d_out, int out_size) {
    const float* pred = (const float*)d_in[0];
    const void*  tgt  = d_in[1];
    float* out = (float*)d_out;

    dcl_fused<<<4096, 512>>>(pred, tgt, out);
}

// round 11
// speedup vs baseline: 1.1062x; 1.0393x over previous
#include <cuda_runtime.h>

#define BATCH 8
#define NCH   6
#define HH    1024
#define WW    1024
#define TX    64
#define TY    64
#define HY    68      // halo rows: [by-2, by+66)
#define NPIX  (8.0f * 1024.0f * 1024.0f)
#define PIX_PER_B (HH * WW)          // 1<<20
#define CH_STRIDE4 (PIX_PER_B / 4)   // 262144
#define NSTENCIL 2048

__device__ unsigned g_code4[(BATCH * PIX_PER_B) / 4];   // 8 MiB
__device__ int   g_cnt[BATCH];    // classify blocks completed per batch
__device__ int   g_done;          // stencil tiles completed
__device__ float g_partial;       // loss accumulator

// One fused kernel, 4096 blocks x 512 threads, >=3 blocks/SM (48 warps for MLP).
// Every block classifies its 2 rows of its batch (batch = bid>>9).
// Stencil tiles are shifted one batch back so waits are ~free:
//   bid in [512(b+1), 512(b+1)+256) -> tile (bid&255) of batch b, b=0..6
//   bid in [3840+256, 4096)         -> tile (bid&511)-256 of batch 7 (tail)
__global__ __launch_bounds__(512, 3) void dcl_fused(
    const float* __restrict__ pred, const void* __restrict__ tgt,
    float* __restrict__ out)
{
    const int tid   = threadIdx.x;
    const int bid   = blockIdx.x;
    const int batch = bid >> 9;

    // ================= Phase 1: classify (streaming argmax + pack) ==========
    {
        // Targets in [0,5]; little-endian int64 => odd 32-bit words of the
        // first 64 elements all zero. P(false positive int32) = (1/6)^32 ~ 0.
        const int lane  = tid & 31;
        const int probe = ((const int*)tgt)[2 * lane + 1];
        const int is64  = (__ballot_sync(0xffffffffu, probe != 0) == 0u);

        const unsigned t   = (unsigned)bid * 512u + tid;   // pixel4 index
        const unsigned off = t & 0x3FFFFu;

        const float4* pp = (const float4*)pred + (size_t)batch * NCH * CH_STRIDE4 + off;
        float4 v[NCH];
        #pragma unroll
        for (int ch = 0; ch < NCH; ++ch) v[ch] = pp[(size_t)ch * CH_STRIDE4];

        int t0, t1, t2, t3;
        if (is64) {
            const int4* tp = (const int4*)tgt + (size_t)t * 2;
            const int4 q0 = tp[0], q1 = tp[1];
            t0 = q0.x; t1 = q0.z; t2 = q1.x; t3 = q1.z;
        } else {
            const int4 q = ((const int4*)tgt)[t];
            t0 = q.x; t1 = q.y; t2 = q.z; t3 = q.w;
        }

        int i0 = 0, i1 = 0, i2 = 0, i3 = 0;
        float m0 = v[0].x, m1 = v[0].y, m2 = v[0].z, m3 = v[0].w;
        #pragma unroll
        for (int ch = 1; ch < NCH; ++ch) {
            if (v[ch].x > m0) { m0 = v[ch].x; i0 = ch; }
            if (v[ch].y > m1) { m1 = v[ch].y; i1 = ch; }
            if (v[ch].z > m2) { m2 = v[ch].z; i2 = ch; }
            if (v[ch].w > m3) { m3 = v[ch].w; i3 = ch; }
        }

        g_code4[t] = (unsigned)(i0 | (t0 << 4))
                   | ((unsigned)(i1 | (t1 << 4)) << 8)
                   | ((unsigned)(i2 | (t2 << 4)) << 16)
                   | ((unsigned)(i3 | (t3 << 4)) << 24);
    }

    // Release: publish this block's code words, then count the block.
    __threadfence();
    __syncthreads();
    if (tid == 0) atomicAdd(&g_cnt[batch], 1);

    // ================= Stencil tile assignment ==============================
    const int half = bid & 511;
    int tb, tile;
    if (batch >= 1 && half < 256)       { tb = batch - 1; tile = half; }
    else if (batch == 7 && half >= 256) { tb = 7;         tile = half - 256; }
    else return;                        // classify-only block

    // Wait: target batch fully classified (usually already done for tb<7).
    if (tid == 0) {
        int v;
        do {
            asm volatile("ld.acquire.gpu.s32 %0, [%1];"
                         : "=r"(v) : "l"(g_cnt + tb) : "memory");
            if (v >= 512) break;
            __nanosleep(128);
        } while (1);
    }
    __syncthreads();

    // ================= Phase 2: stencil tile + reduce =======================
    // hbuf[r][c]: 4 x 8-bit fields = h5sum(cv) | h5sum(cv^2)<<8
    //                              | h5sum(tv)<<16 | h5sum(tv^2)<<24
    // (<=25 / <=125 / <=25 / <=125 — no field carry.)
    __shared__ unsigned hbuf[HY][TX];   // 17.4 KB

    const int bx = (tile & 15) * TX;
    const int by = (tile >> 4) * TY;
    const unsigned base_w = (unsigned)tb << 18;

    for (int i = tid; i < HY * (TX / 4); i += 512) {
        const int rr = i >> 4;              // halo row 0..67
        const int cw = i & 15;              // word-col within tile
        const int gy = by + rr - 2;
        unsigned wm = 0, w0 = 0, wp = 0;
        if ((unsigned)gy < (unsigned)HH) {
            const unsigned rowbase = base_w + ((unsigned)gy << 8);
            const int wc = (bx >> 2) + cw;  // 0..255
            if (wc > 0)   wm = g_code4[rowbase + wc - 1];
            w0 = g_code4[rowbase + wc];
            if (wc < 255) wp = g_code4[rowbase + wc + 1];
        }
        // code bytes covering cols gx-2..gx+5
        unsigned e[8];
        e[0] = (wm >> 16) & 255u;  e[1] = wm >> 24;
        e[2] =  w0        & 255u;  e[3] = (w0 >> 8) & 255u;
        e[4] = (w0 >> 16) & 255u;  e[5] =  w0 >> 24;
        e[6] =  wp        & 255u;  e[7] = (wp >> 8) & 255u;
        unsigned m[8];
        #pragma unroll
        for (int j = 0; j < 8; ++j) {
            const unsigned cv = e[j] & 15u, tv = e[j] >> 4;
            m[j] = cv * ((cv << 8) + 1u) + ((tv * ((tv << 8) + 1u)) << 16);
        }
        unsigned s = m[0] + m[1] + m[2] + m[3] + m[4];
        uint4 o;
        o.x = s; s += m[5] - m[0];
        o.y = s; s += m[6] - m[1];
        o.z = s; s += m[7] - m[2];
        o.w = s;
        *(uint4*)&hbuf[rr][cw * 4] = o;
    }
    __syncthreads();

    // Vertical sliding 5-window: 1 col x 8 rows per thread.
    // Split each h-word into lo = s1c|s1t<<16 and hi = s2c|s2t<<16 (16-bit
    // fields; vertical 5-sums reach 125 / 625 — no carry).
    const int c  = tid & 63;
    const int r0 = (tid >> 6) * 8;

    unsigned lo[12], hi[12];
    #pragma unroll
    for (int d = 0; d < 12; ++d) {
        const unsigned w = hbuf[r0 + d][c];
        lo[d] = w & 0x00FF00FFu;
        hi[d] = (w >> 8) & 0x00FF00FFu;
    }
    unsigned sa = lo[0] + lo[1] + lo[2] + lo[3] + lo[4];
    unsigned sb = hi[0] + hi[1] + hi[2] + hi[3] + hi[4];

    int   acc_i = 0;
    float acc_s = 0.0f;
    #pragma unroll
    for (int rr = 0; rr < 8; ++rr) {
        // q = 25*sb evaluates both 25*s2 fields at once (25*625=15625 < 2^16).
        const unsigned q = sb * 25u;
        const int s1c = (int)(sa & 0xFFFFu), s1t = (int)(sa >> 16);
        const int np = (int)(q & 0xFFFFu) - s1c * s1c;   // exact, [0,15625]
        const int nt = (int)(q >> 16)     - s1t * s1t;
        acc_i += np + nt;
        // (sqrt(np/600)-sqrt(nt/600))^2 = (np + nt - 2*sqrt(np*nt))/600
        const float p = (float)(np * nt);
        float s;
        asm("sqrt.approx.f32 %0, %1;" : "=f"(s) : "f"(p));
        acc_s += s;
        if (rr < 7) { sa += lo[rr + 5] - lo[rr]; sb += hi[rr + 5] - hi[rr]; }
    }

    float acc = fmaf(-2.0f, acc_s, (float)acc_i) * (1.0f / (600.0f * NPIX));

    #pragma unroll
    for (int o = 16; o > 0; o >>= 1)
        acc += __shfl_down_sync(0xffffffffu, acc, o);

    __shared__ float warpsum[16];
    if ((tid & 31) == 0) warpsum[tid >> 5] = acc;
    __syncthreads();
    if (tid < 16) {
        float v = warpsum[tid];
        #pragma unroll
        for (int o = 8; o > 0; o >>= 1)
            v += __shfl_down_sync(0xffffu, v, o);
        if (tid == 0) {
            atomicAdd(&g_partial, v);
            __threadfence();
            const int old = atomicAdd(&g_done, 1);
            if (old == NSTENCIL - 1) {
                // All tiles done (each fenced before its g_done inc): publish
                // and reset ALL state for the next graph replay.
                *out = *(volatile float*)&g_partial;
                g_partial = 0.0f;
                #pragma unroll
                for (int i = 0; i < BATCH; ++i) g_cnt[i] = 0;
                g_done = 0;
                __threadfence();
            }
        }
    }
}

extern "C" void kernel_launch(void* const* d_in, const int* in_sizes, int n_in,
                              void* d_out, int out_size) {
    const float* pred = (const float*)d_in[0];
    const void*  tgt  = d_in[1];
    float* out = (float*)d_out;

    dcl_fused<<<4096, 512>>>(pred, tgt, out);
}